// round 13
// baseline (speedup 1.0000x reference)
#include <cuda_runtime.h>

#define S_SRC 16384
#define T_GRID 4096
#define NHBR 8
#define BATCH 4
#define EDIM 16
#define GBINS 64
#define NBINS (GBINS * GBINS)
#define CELL (1.0f / 64.0f)
#define BCAP 32
#define MEGA_BLOCKS 256

// Scratch (static device globals — no allocation). g_cnt zero-initialized at
// load; re-zeroed each launch by interp_kernel block 0 for graph replays.
// Barrier generation only ever increments (replay-safe); count self-resets.
__device__ float  g_xg[BATCH * T_GRID * EDIM];
__device__ int    g_cnt[NBINS];
__device__ float2 g_bxy[NBINS * BCAP];
__device__ int    g_bidx[NBINS * BCAP];
__device__ int    g_bar_count = 0;
__device__ int    g_bar_gen = 0;

__device__ __forceinline__ int clampb(int v) { return min(max(v, 0), GBINS - 1); }

// Grid-wide barrier over MEGA_BLOCKS co-resident blocks (generation-based;
// proven in R6). launch_bounds(256,2) + 18KB smem guarantee 2 blocks/SM ->
// 296 slots >= 256 blocks: never deadlocks.
__device__ __forceinline__ void grid_barrier() {
  __syncthreads();
  if (threadIdx.x == 0) {
    __threadfence();
    const int gen = atomicAdd(&g_bar_gen, 0);
    if (atomicAdd(&g_bar_count, 1) == MEGA_BLOCKS - 1) {
      atomicExch(&g_bar_count, 0);
      __threadfence();
      atomicAdd(&g_bar_gen, 1);
    } else {
      while (atomicAdd(&g_bar_gen, 0) == gen) {
      }
    }
    __threadfence();
  }
  __syncthreads();
}

// ---------------------------------------------------------------------------
// kNN helpers (R9 warp-uniform versions).
// Key = (f32bits(d2)<<32)|idx reproduces lax.top_k(-d2) order + tie-break.
// ---------------------------------------------------------------------------
__device__ __forceinline__ void insert_key(unsigned long long key,
                                           unsigned long long best[8],
                                           float& worst) {
  if (key < best[7]) {
    best[7] = key;
#pragma unroll
    for (int k = 7; k > 0; k--) {
      unsigned long long lo = (best[k] < best[k - 1]) ? best[k] : best[k - 1];
      unsigned long long hi = (best[k] < best[k - 1]) ? best[k - 1] : best[k];
      best[k - 1] = lo;
      best[k] = hi;
    }
    worst = __uint_as_float((unsigned)(best[7] >> 32));
  }
}

__device__ __forceinline__ void try_candidate(int slot, float gx, float gy,
                                              unsigned long long best[8],
                                              float& worst) {
  const float2 p = g_bxy[slot];
  const float dx = gx - p.x;
  const float dy = gy - p.y;
  const float d2 = fmaf(dy, dy, dx * dx);
  if (d2 <= worst) {
    unsigned long long key =
        ((unsigned long long)__float_as_uint(d2) << 32) | (unsigned)g_bidx[slot];
    insert_key(key, best, worst);
  }
}

__device__ __forceinline__ unsigned long long merge8_32(
    const unsigned long long best[8], int lane, unsigned long long& mine) {
  unsigned long long cand = best[0];
  int p = 0;
  unsigned long long m = 0;
#pragma unroll
  for (int k = 0; k < 8; k++) {
    m = cand;
#pragma unroll
    for (int off = 16; off > 0; off >>= 1) {
      unsigned long long o = __shfl_xor_sync(0xffffffffu, m, off);
      m = (o < m) ? o : m;
    }
    if (lane == k) mine = m;
    if (cand == m) {
      p++;
      cand = (p < 8) ? best[p] : 0xFFFFFFFFFFFFFFFFULL;
    }
  }
  return m;
}

// ---------------------------------------------------------------------------
// MEGA kernel: bins -> grid barrier -> per-warp [knn -> weights -> xg] x2.
// 256 blocks x 256 threads = 2048 warps; each warp owns grid points w, w+2048.
// After the barrier each warp is fully autonomous: neighbor indices stay in
// registers (shfl from `mine`), softmax weights distributed by shfl.
// wx phase: lane = n*4 + h2 (R12 layout, conflict-free smem tables).
// ---------------------------------------------------------------------------
__global__ __launch_bounds__(256, 2) void mega_kernel(
    const float* __restrict__ x,
    const float* __restrict__ cs, const float* __restrict__ cg,
    const float* __restrict__ w1, const float* __restrict__ b1,
    const float* __restrict__ w2, const float* __restrict__ b2,
    const float* __restrict__ lng, const float* __restrict__ lnb,
    const float* __restrict__ kw, const float* __restrict__ kb) {
  __shared__ float sW1[128];
  __shared__ float sB1[64];
  __shared__ float4 sW2p[520];     // 4 groups x (16j * 8q) + pad 2/group
  __shared__ float sKWt[8 * 264];  // [j][n(33-stride)][d] conflict-free
  __shared__ float sB2[32], sLNG[32], sLNB[32], sKB[8];

  const int tid = threadIdx.x;
  // Weight tables (once per block; overlaps the bins phase + barrier wait).
  if (tid < 128) sW1[tid] = w1[tid];
  if (tid < 64) sB1[tid] = b1[tid];
  for (int i = tid; i < 512; i += 256) {
    const int j = i >> 3, q = i & 7;
    sW2p[(j >> 4) * 130 + (j & 15) * 8 + q] = ((const float4*)w2)[i];
  }
  for (int i = tid; i < 2048; i += 256) {
    const int row = i >> 3, j = i & 7;
    sKWt[j * 264 + (row >> 5) * 33 + (row & 31)] = kw[i];
  }
  if (tid < 32) {
    sB2[tid] = b2[tid];
    sLNG[tid] = lng[tid];
    sLNB[tid] = lnb[tid];
  }
  if (tid < 8) sKB[tid] = kb[tid];

  // ---- Phase 0: bins (first 16384 threads; g_cnt zeroed by prior replay) ----
  const int gid = blockIdx.x * 256 + tid;
  if (gid < S_SRC) {
    const float px = cs[gid];
    const float py = cs[S_SRC + gid];
    const int bb = clampb((int)(px * (float)GBINS)) * GBINS +
                   clampb((int)(py * (float)GBINS));
    const int p = atomicAdd(&g_cnt[bb], 1);
    if (p < BCAP) {
      g_bxy[bb * BCAP + p] = make_float2(px, py);
      g_bidx[bb * BCAP + p] = gid;
    }
  }
  grid_barrier();

  const int wrp = blockIdx.x * 8 + (tid >> 5);  // 0..2047
  const int lane = tid & 31;
  const int n = lane >> 2;   // neighbor 0..7
  const int h2 = lane & 3;   // hidden quarter 0..3

#pragma unroll
  for (int rep = 0; rep < 2; rep++) {
    const int t = wrp + rep * 2048;

    // ---- kNN (warp-uniform) ----
    const float gx = cg[t];
    const float gy = cg[T_GRID + t];
    const int hbx = clampb((int)(gx * (float)GBINS));
    const int hby = clampb((int)(gy * (float)GBINS));

    unsigned long long best[8];
#pragma unroll
    for (int i = 0; i < 8; i++) best[i] = 0x7F800000FFFFFFFFULL;
    float worst = __int_as_float(0x7F800000);

    int myCnt = 0, myBase = 0;
    if (lane < 9) {
      const int bx = hbx + (lane % 3) - 1;
      const int by = hby + (lane / 3) - 1;
      if (bx >= 0 && bx < GBINS && by >= 0 && by < GBINS) {
        const int bb = bx * GBINS + by;
        myCnt = min(g_cnt[bb], BCAP);
        myBase = bb * BCAP;
      }
    }
#pragma unroll
    for (int i = 0; i < 9; i++) {
      const int cnt = __shfl_sync(0xffffffffu, myCnt, i);
      const int base = __shfl_sync(0xffffffffu, myBase, i);
      for (int c = lane; c < cnt; c += 32)
        try_candidate(base + c, gx, gy, best, worst);
    }

    unsigned long long mine = 0;
    unsigned long long m8 = merge8_32(best, lane, mine);
    float gw = __uint_as_float((unsigned)(m8 >> 32));

    for (int r = 2; r < GBINS; r++) {
      const float dmin = (float)(r - 1) * CELL;
      if (dmin * dmin > gw) break;
      const int nring = 8 * r;
      for (int idx = lane; idx < nring; idx += 32) {
        const int seg = idx / (2 * r);
        const int off = idx - seg * 2 * r;
        int dx, dy;
        if (seg == 0) { dx = -r + off; dy = -r; }
        else if (seg == 1) { dx = -r + 1 + off; dy = r; }
        else if (seg == 2) { dx = -r; dy = -r + 1 + off; }
        else { dx = r; dy = -r + off; }
        const int bx = hbx + dx, by = hby + dy;
        if (bx < 0 || bx >= GBINS || by < 0 || by >= GBINS) continue;
        const int bb = bx * GBINS + by;
        const int cnt = min(g_cnt[bb], BCAP);
        const int base = bb * BCAP;
        for (int c = 0; c < cnt; c++)
          try_candidate(base + c, gx, gy, best, worst);
      }
      m8 = merge8_32(best, lane, mine);
      gw = __uint_as_float((unsigned)(m8 >> 32));
    }
    const int mine_idx = (int)(mine & 0xFFFFFFFFu);  // valid at lanes 0..7

    // ---- weights: PE MLP (quarter j-range per lane) -> LN -> logits ----
    const int si = __shfl_sync(0xffffffffu, mine_idx, n);
    const float r0 = cs[si] - gx;
    const float r1 = cs[S_SRC + si] - gy;

    float pe[32];
#pragma unroll
    for (int d = 0; d < 32; d++) pe[d] = (h2 == 0) ? sB2[d] : 0.0f;

    const int jbase = h2 << 4;
    const int gbase4 = h2 * 130;
#pragma unroll 2
    for (int jj = 0; jj < 16; jj++) {
      const int j = jbase + jj;
      float hv = fmaf(r1, sW1[64 + j], fmaf(r0, sW1[j], sB1[j]));
      float z = 0.7978845608028654f * fmaf(0.044715f, hv * hv * hv, hv);
      float g = hv * __fdividef(1.0f, 1.0f + __expf(-2.0f * z));  // gelu_tanh
#pragma unroll
      for (int q = 0; q < 8; q++) {
        float4 wv = sW2p[gbase4 + jj * 8 + q];
        pe[q * 4 + 0] = fmaf(g, wv.x, pe[q * 4 + 0]);
        pe[q * 4 + 1] = fmaf(g, wv.y, pe[q * 4 + 1]);
        pe[q * 4 + 2] = fmaf(g, wv.z, pe[q * 4 + 2]);
        pe[q * 4 + 3] = fmaf(g, wv.w, pe[q * 4 + 3]);
      }
    }
#pragma unroll
    for (int d = 0; d < 32; d++) {
      pe[d] += __shfl_xor_sync(0xffffffffu, pe[d], 1);
      pe[d] += __shfl_xor_sync(0xffffffffu, pe[d], 2);
    }

    float mu = 0.f;
#pragma unroll
    for (int d = 0; d < 32; d++) mu += pe[d];
    mu *= (1.0f / 32.0f);
    float var = 0.f;
#pragma unroll
    for (int d = 0; d < 32; d++) {
      float c = pe[d] - mu;
      var = fmaf(c, c, var);
    }
    var *= (1.0f / 32.0f);
    const float rstd = rsqrtf(var + 1e-5f);
#pragma unroll
    for (int d = 0; d < 32; d++)
      pe[d] = fmaf((pe[d] - mu) * rstd, sLNG[d], sLNB[d]);

    const int j0 = h2 << 1;
    float pl0 = 0.f, pl1 = 0.f;
    const float* kt0 = sKWt + j0 * 264 + n * 33;
    const float* kt1 = kt0 + 264;
#pragma unroll
    for (int d = 0; d < 32; d++) {
      pl0 = fmaf(pe[d], kt0[d], pl0);
      pl1 = fmaf(pe[d], kt1[d], pl1);
    }
#pragma unroll
    for (int off = 4; off <= 16; off <<= 1) {
      pl0 += __shfl_xor_sync(0xffffffffu, pl0, off);
      pl1 += __shfl_xor_sync(0xffffffffu, pl1, off);
    }
    pl0 += sKB[j0];
    pl1 += sKB[j0 + 1];
    const float q0 = __shfl_xor_sync(0xffffffffu, pl0, 1);
    const float q1 = __shfl_xor_sync(0xffffffffu, pl1, 1);
    const float s0 = __shfl_xor_sync(0xffffffffu, pl0, 2);
    const float s1 = __shfl_xor_sync(0xffffffffu, pl1, 2);
    const float u0 = __shfl_xor_sync(0xffffffffu, q0, 2);
    const float u1 = __shfl_xor_sync(0xffffffffu, q1, 2);

    float mx = fmaxf(fmaxf(fmaxf(pl0, pl1), fmaxf(q0, q1)),
                     fmaxf(fmaxf(s0, s1), fmaxf(u0, u1)));
    const float e0 = __expf(pl0 - mx);
    const float e1 = __expf(pl1 - mx);
    const float ssum = e0 + e1 + __expf(q0 - mx) + __expf(q1 - mx) +
                       __expf(s0 - mx) + __expf(s1 - mx) + __expf(u0 - mx) +
                       __expf(u1 - mx);
    const float inv = __fdividef(1.0f, ssum);
    const float e0i = e0 * inv;  // weight for output 2*h2 (lanes n=0..7 equal)
    const float e1i = e1 * inv;  // weight for output 2*h2+1

    // ---- xg gather: lane = (batch, oct); weights+indices via shfl ----
    const int bidx = lane >> 3;  // 0..3
    const int oct = lane & 7;    // 0..7
    float ax = 0.f, ay = 0.f;
    const float* xb = x + (size_t)bidx * S_SRC * EDIM + oct * 2;
#pragma unroll
    for (int nn = 0; nn < NHBR; nn++) {
      const int s = __shfl_sync(0xffffffffu, mine_idx, nn);
      const float wa = __shfl_sync(0xffffffffu, e0i, nn >> 1);
      const float wb = __shfl_sync(0xffffffffu, e1i, nn >> 1);
      const float wgt = (nn & 1) ? wb : wa;
      const float2 v = *(const float2*)(xb + (size_t)s * EDIM);
      ax = fmaf(wgt, v.x, ax);
      ay = fmaf(wgt, v.y, ay);
    }
    *(float2*)(g_xg + (size_t)((bidx << 12) + t) * EDIM + oct * 2) =
        make_float2(ax, ay);
  }
}

// ---------------------------------------------------------------------------
// Gaussian axis window, factorized (identical math to R9).
// ---------------------------------------------------------------------------
__device__ __forceinline__ void fma4(float4& a, float w, const float4 v) {
  a.x = fmaf(w, v.x, a.x);
  a.y = fmaf(w, v.y, a.y);
  a.z = fmaf(w, v.z, a.z);
  a.w = fmaf(w, v.w, a.w);
}

__device__ __forceinline__ void axis_weights(float pos, float rp,
                                             const float* __restrict__ sC,
                                             float w[5]) {
  const float delta = rp - pos;
  const float lnr = -(20.0f / 89.0f) * delta;
  const float r = __expf(lnr);

  float S0 = 0.f, S1 = 0.f, S2 = 0.f, S3 = 0.f, S4 = 0.f;
  float rr = 1.0f;
#pragma unroll
  for (int k = 0; k < 18; k++) {
    S0 = fmaf(sC[k], rr, S0);
    S1 = fmaf(sC[18 + k], rr, S1);
    S2 = fmaf(sC[36 + k], rr, S2);
    S3 = fmaf(sC[54 + k], rr, S3);
    S4 = fmaf(sC[72 + k], rr, S4);
    rr *= r;
  }
  const float q = rr;
  const float q2 = q * q;
  w[0] = S0;
  w[1] = q * S1;
  w[2] = q2 * S2;
  w[3] = q2 * q * S3;
  w[4] = q2 * q2 * S4;

  const int irp = (int)rp;
  if (irp <= 2 || irp >= 62) {
    const float G = __expf(fmaf(-2.0f * delta, delta, 10.0f * delta));
#pragma unroll
    for (int i = 0; i < 5; i++) w[i] *= G;
    if (irp <= 2) {
      const int j0 = (int)ceilf((2.5f - rp) * 17.8f);
      const float K = __expf(-2.0f * pos * pos);
      float rj = G;
#pragma unroll
      for (int i = 0; i < 5; i++) {
        const int jlo = i * 18;
        const int jhi = min(j0, jlo + 18);
        float c = 0.f;
        for (int j = jlo; j < jhi; j++) {
          c += K - sC[j] * rj;
          rj *= r;
        }
        w[i] += c;
      }
    } else {
      const float d64 = 64.0f - pos;
      const float K = __expf(-2.0f * d64 * d64);
      const int jc = (int)floorf((66.5f - rp) * 17.8f) + 1;
      float rjj = G * __expf(lnr * (float)jc);
#pragma unroll
      for (int i = 0; i < 5; i++) {
        const int jlo = max(jc, i * 18);
        const int jhi = (i + 1) * 18;
        float c = 0.f;
        for (int j = jlo; j < jhi; j++) {
          c += K - sC[j] * rjj;
          rjj *= r;
        }
        w[i] += c;
      }
    }
  }
}

// ---------------------------------------------------------------------------
// Gaussian-window resampling (R9 shape, unchanged). FOUR threads per (b, n).
// Zeroes g_cnt (block 0) for the next graph replay.
// ---------------------------------------------------------------------------
__global__ __launch_bounds__(256, 4) void interp_kernel(
    const float* __restrict__ ct, float* __restrict__ out) {
  __shared__ float sC[90];
  {
    const int tt = threadIdx.x;
    if (tt < 90) {
      float off = fmaf((float)tt, -5.0f / 89.0f, 2.5f);
      sC[tt] = __expf(-2.0f * off * off);
    }
    if (blockIdx.x == 0) {
      for (int i = tt; i < NBINS; i += 256) g_cnt[i] = 0;
    }
  }
  __syncthreads();

  const int gid4 = blockIdx.x * 256 + threadIdx.x;  // 131072 = 4*B*N
  const int tgt = gid4 >> 2;
  const int quad = gid4 & 3;
  const int b = tgt >> 13;
  const float2 c2 = ((const float2*)ct)[tgt];
  const float posx = c2.y * 63.0f;
  const float posy = c2.x * 63.0f;
  const float rpx = rintf(posx);
  const float rpy = rintf(posy);

  float wx[5], wy[5];
  axis_weights(posx, rpx, sC, wx);
  axis_weights(posy, rpy, sC, wy);

  const float sx = wx[0] + wx[1] + wx[2] + wx[3] + wx[4];
  const float sy = wy[0] + wy[1] + wy[2] + wy[3] + wy[4];
  const float inv = 1.0f / (sx * sy);

  int ixi[5], iyi[5];
  const int irpx = (int)rpx;
  const int irpy = (int)rpy;
#pragma unroll
  for (int k = 0; k < 5; k++) {
    ixi[k] = min(max(irpx + 2 - k, 0), 63);
    iyi[k] = min(max(irpy + 2 - k, 0), 63);
  }

  float4 acc = {0, 0, 0, 0};
  const float* gbase = g_xg + (size_t)b * (T_GRID * EDIM) + quad * 4;
#pragma unroll
  for (int kx = 0; kx < 5; kx++) {
    const int rowbase = ixi[kx] << 6;
    const float wxk = wx[kx] * inv;
#pragma unroll
    for (int ky = 0; ky < 5; ky++) {
      const float wc = wxk * wy[ky];
      const float4 v =
          *(const float4*)(gbase + (size_t)(rowbase + iyi[ky]) * EDIM);
      fma4(acc, wc, v);
    }
  }
  ((float4*)(out + (size_t)tgt * EDIM))[quad] = acc;
}

// ---------------------------------------------------------------------------
extern "C" void kernel_launch(void* const* d_in, const int* in_sizes, int n_in,
                              void* d_out, int out_size) {
  const float* x   = (const float*)d_in[0];
  const float* cs  = (const float*)d_in[1];
  const float* cg  = (const float*)d_in[2];
  const float* ct  = (const float*)d_in[3];
  const float* w1  = (const float*)d_in[4];
  const float* b1  = (const float*)d_in[5];
  const float* w2  = (const float*)d_in[6];
  const float* b2  = (const float*)d_in[7];
  const float* lng = (const float*)d_in[8];
  const float* lnb = (const float*)d_in[9];
  const float* kw  = (const float*)d_in[10];
  const float* kb  = (const float*)d_in[11];
  float* out = (float*)d_out;

  mega_kernel<<<MEGA_BLOCKS, 256>>>(x, cs, cg, w1, b1, w2, b2, lng, lnb, kw, kb);
  interp_kernel<<<512, 256>>>(ct, out);
}